// round 17
// baseline (speedup 1.0000x reference)
#include <cuda_runtime.h>
#include <cuda_fp16.h>

#define Bq   512
#define Tt   365
#define Ff   16
#define Hh   256
#define G4   1024
#define CLU  8       // CTAs per cluster (gate-col split 8-way)
#define NCg  128     // CTAs total (16 clusters x 8)
#define MB   32      // batch rows per cluster (2 M-tiles per CTA)
#define NT   512     // 16 warps; warp owns 8 packed cols (1 n8-tile) x 2 M-tiles
#define K1T  17      // layer-1 k-tiles (272 = 16 x + 256 h1)
#define HST  536     // buffer col stride (halves): [x 16 | h1 256 | h2 256 | pad]
#define H1OFF 16
#define H2OFF 272
#define KTS  4096    // uint2 frag stride per kt (8*16*32)

// ---------------------------------------------------------------------------
// fp16 B fragments (m16n8k16 .col), gate-interleaved, 8-way CLUSTER-SPLIT:
//   packed col P = r*128 + w*8 + n ; gate = n&3, unit = r*32 + w*2 + (n>>2)
//   frag uint2 idx = ((kt*8 + r)*16 + w)*32 + lane ->
//     4 halves = B[k0+2m][c], B[k0+2m+1][c], B[k0+2m+8][c], B[k0+2m+9][c],
//     c = P of (lane>>2), m = lane&3
// ---------------------------------------------------------------------------
__device__ __align__(16) __half g_wb1[(Ff + Hh) * G4];
__device__ __align__(16) __half g_wb2[2 * Hh * G4];
__device__ float g_b1p[G4];
__device__ float g_b2p[G4];

__device__ __forceinline__ float sigf(float x) {
    return __fdividef(1.0f, 1.0f + __expf(-x));
}
__device__ __forceinline__ float tanhg(float x) {
    return __fdividef(2.0f, 1.0f + __expf(-2.0f * x)) - 1.0f;
}
__device__ __forceinline__ unsigned s2u(const void* p) {
    unsigned a;
    asm("{ .reg .u64 t; cvta.to.shared.u64 t, %1; cvt.u32.u64 %0, t; }" : "=r"(a) : "l"(p));
    return a;
}
__device__ __forceinline__ void ldsm4(unsigned& a0, unsigned& a1, unsigned& a2, unsigned& a3,
                                      unsigned addr) {
    asm volatile("ldmatrix.sync.aligned.m8n8.x4.shared.b16 {%0,%1,%2,%3}, [%4];"
                 : "=r"(a0), "=r"(a1), "=r"(a2), "=r"(a3) : "r"(addr));
}
__device__ __forceinline__ void mma16816(float& d0, float& d1, float& d2, float& d3,
                                         unsigned a0, unsigned a1, unsigned a2, unsigned a3,
                                         unsigned b0, unsigned b1) {
    asm volatile("mma.sync.aligned.m16n8k16.row.col.f32.f16.f16.f32 "
                 "{%0,%1,%2,%3}, {%4,%5,%6,%7}, {%8,%9}, {%0,%1,%2,%3};"
                 : "+f"(d0), "+f"(d1), "+f"(d2), "+f"(d3)
                 : "r"(a0), "r"(a1), "r"(a2), "r"(a3), "r"(b0), "r"(b1));
}
__device__ __forceinline__ void sts16(unsigned addr, __half v) {
    asm volatile("st.shared.b16 [%0], %1;" :: "r"(addr), "h"(__half_as_ushort(v)) : "memory");
}
#define CL_ARRIVE() asm volatile("barrier.cluster.arrive.aligned;" ::: "memory")
#define CL_WAIT()   asm volatile("barrier.cluster.wait.aligned;"   ::: "memory")

// ---------------------------------------------------------------------------
// Prep: pack B uint2 fragments (8-way split cols) + packed biases.
// ---------------------------------------------------------------------------
__global__ void prep_kernel(const float* __restrict__ wih1, const float* __restrict__ whh1,
                            const float* __restrict__ bih1, const float* __restrict__ bhh1,
                            const float* __restrict__ wih2, const float* __restrict__ whh2,
                            const float* __restrict__ bih2, const float* __restrict__ bhh2) {
    int idx = blockIdx.x * blockDim.x + threadIdx.x;   // uint2 idx, over 32*4096 = 131072
    int lane = idx & 31, w = (idx >> 5) & 15, r = (idx >> 9) & 7, kt = idx >> 12;
    int m = lane & 3, n = lane >> 2;                   // n in [0,8)
    int oc = (n & 3) * 256 + r * 32 + w * 2 + (n >> 2);
    int k0 = kt * 16;
    int ks[4] = {k0 + 2 * m, k0 + 2 * m + 1, k0 + 2 * m + 8, k0 + 2 * m + 9};

    if (kt < 32) {
        __align__(8) __half h[4];
        #pragma unroll
        for (int j = 0; j < 4; ++j) {
            int k = ks[j];
            h[j] = __float2half_rn((k < Hh) ? wih2[oc * Hh + k] : whh2[oc * Hh + (k - Hh)]);
        }
        *((uint2*)g_wb2 + idx) = *(const uint2*)h;
    }
    if (kt < K1T) {
        __align__(8) __half h[4];
        #pragma unroll
        for (int j = 0; j < 4; ++j) {
            int k = ks[j];
            h[j] = __float2half_rn((k < Ff) ? wih1[oc * Ff + k] : whh1[oc * Hh + (k - Ff)]);
        }
        *((uint2*)g_wb1 + idx) = *(const uint2*)h;
    }
    if (idx < G4) {
        int P = idx;
        int rb = P >> 7, wb = (P >> 3) & 15, nb = P & 7;
        int ocb = (nb & 3) * 256 + rb * 32 + wb * 2 + (nb >> 2);
        g_b1p[P] = bih1[ocb] + bhh1[ocb];
        g_b2p[P] = bih2[ocb] + bhh2[ocb];
    }
}

// ---------------------------------------------------------------------------
// Fused 2-layer LSTM; 8-way cluster split, 32 batch rows per cluster,
// split-phase barriers, waits hidden under MMA blocks.
// ---------------------------------------------------------------------------
__global__ void __cluster_dims__(CLU, 1, 1) __launch_bounds__(NT, 1)
lstm_kernel(const float* __restrict__ x,
            const float* __restrict__ wlin, const float* __restrict__ blin,
            float* __restrict__ out) {
    __shared__ __align__(16) __half buf[MB * HST];   // [32 rows][x|h1|h2]

    const int tid  = threadIdx.x;
    const int lane = tid & 31;
    const int w    = tid >> 5;
    const int m    = lane & 3;
    const int g    = lane >> 2;
    const bool modd = (m & 1);
    unsigned rank; asm("mov.u32 %0, %%cluster_ctarank;" : "=r"(rank));
    const int b0   = (blockIdx.x >> 3) * MB;

    for (int i = tid; i < MB * HST; i += NT) buf[i] = __ushort_as_half(0);

    float c1[2] = {0.f, 0.f};     // [mt]
    float c2[2] = {0.f, 0.f};

    const unsigned sbase = s2u(buf);
    const int lr  = (lane & 7) + 8 * ((lane >> 3) & 1);
    const int lc8 = (lane >> 4) * 8;
    const unsigned aBase0 = sbase + (unsigned)(lr * HST + lc8) * 2u;
    const unsigned aBase1 = aBase0 + (unsigned)(16 * HST) * 2u;

    const uint2* wb1 = (const uint2*)g_wb1 + ((int)rank * 16 + w) * 32 + lane;
    const uint2* wb2 = (const uint2*)g_wb2 + ((int)rank * 16 + w) * 32 + lane;
    const int PB = (int)rank * 128 + w * 8;

    const float2 b1v = *(const float2*)&g_b1p[PB + 2 * m];
    const float2 b2v = *(const float2*)&g_b2p[PB + 2 * m];

    // update identity: row = g / g+8 (+16*mt); unit = rank*32 + w*2 + (m>>1)
    const int urow = modd ? (g + 8) : g;
    const unsigned h1addr = sbase + (unsigned)(urow * HST + H1OFF + (int)rank * 32 + w * 2 + (m >> 1)) * 2u;
    const unsigned h2addr = sbase + (unsigned)(urow * HST + H2OFF + (int)rank * 32 + w * 2 + (m >> 1)) * 2u;
    const unsigned mtoff  = (unsigned)(16 * HST) * 2u;

    // peer-copy addressing: one b32 per peer per thread (32 rows x 16 b32)
    const int crow = tid >> 4, cc = tid & 15;
    unsigned cp1_loc[7], cp1_rem[7], cp2_loc[7], cp2_rem[7];
    #pragma unroll
    for (int pp = 1; pp <= 7; ++pp) {
        unsigned pr = rank ^ (unsigned)pp;
        unsigned l1 = sbase + (unsigned)(crow * HST + H1OFF + (int)pr * 32 + cc * 2) * 2u;
        unsigned l2 = sbase + (unsigned)(crow * HST + H2OFF + (int)pr * 32 + cc * 2) * 2u;
        cp1_loc[pp - 1] = l1;  cp2_loc[pp - 1] = l2;
        asm("mapa.shared::cluster.u32 %0, %1, %2;" : "=r"(cp1_rem[pp - 1]) : "r"(l1), "r"(pr));
        asm("mapa.shared::cluster.u32 %0, %1, %2;" : "=r"(cp2_rem[pp - 1]) : "r"(l2), "r"(pr));
    }

    // stage x(0): one value per thread (32*16 = 512)
    {
        int b = tid >> 4, f = tid & 15;
        buf[b * HST + f] = __float2half_rn(__ldg(&x[((size_t)(b0 + b) * Tt) * Ff + f]));
    }
    __syncthreads();

    CL_ARRIVE(); CL_WAIT();   // init visible
    CL_ARRIVE();              // prime first in-loop WAIT

    float acc[2][4];          // [mt][frag]

    for (int t = 0; t < Tt; ++t) {
        // ===== LAYER 1 gates (x + h1(t-1); local) =====
        #pragma unroll
        for (int mt = 0; mt < 2; ++mt) {
            acc[mt][0] = b1v.x; acc[mt][1] = b1v.y; acc[mt][2] = b1v.x; acc[mt][3] = b1v.y;
        }
        for (int kt = 0; kt < K1T; ++kt) {
            uint2 bv = __ldg(wb1 + kt * KTS);
            unsigned a0, a1, a2, a3, e0, e1, e2, e3;
            ldsm4(a0, a1, a2, a3, aBase0 + (unsigned)(kt * 16) * 2u);
            ldsm4(e0, e1, e2, e3, aBase1 + (unsigned)(kt * 16) * 2u);
            mma16816(acc[0][0], acc[0][1], acc[0][2], acc[0][3], a0, a1, a2, a3, bv.x, bv.y);
            mma16816(acc[1][0], acc[1][1], acc[1][2], acc[1][3], e0, e1, e2, e3, bv.x, bv.y);
        }

        // ---- WAIT(#2): peers' h2(t-1) published; copy 7 eighths ----
        CL_WAIT();
        #pragma unroll
        for (int pp = 0; pp < 7; ++pp) {
            unsigned v;
            asm volatile("ld.shared::cluster.b32 %0, [%1];" : "=r"(v) : "r"(cp2_rem[pp]));
            asm volatile("st.shared.b32 [%0], %1;" :: "r"(cp2_loc[pp]), "r"(v) : "memory");
        }
        __syncthreads();   // h2(t-1) full local; all L1 gate reads done

        // ---- L1 update: write OWN h1 eighth ----
        #pragma unroll
        for (int mt = 0; mt < 2; ++mt) {
            float t0 = __shfl_xor_sync(0xffffffffu, acc[mt][0], 1);
            float t1 = __shfl_xor_sync(0xffffffffu, acc[mt][1], 1);
            float t2 = __shfl_xor_sync(0xffffffffu, acc[mt][2], 1);
            float t3 = __shfl_xor_sync(0xffffffffu, acc[mt][3], 1);
            float zi = modd ? t2 : acc[mt][0];
            float zf = modd ? t3 : acc[mt][1];
            float zg = modd ? acc[mt][2] : t0;
            float zo = modd ? acc[mt][3] : t1;
            c1[mt] = sigf(zf) * c1[mt] + sigf(zi) * tanhg(zg);
            float h = sigf(zo) * tanhg(c1[mt]);
            sts16(h1addr + (unsigned)mt * mtoff, __float2half_rn(h));
        }
        CL_ARRIVE();       // #1: own h1(t) eighth published

        // ===== LAYER 2 gates part A: h2(t-1) tiles (kt 16..31; local) =====
        #pragma unroll
        for (int mt = 0; mt < 2; ++mt) {
            acc[mt][0] = b2v.x; acc[mt][1] = b2v.y; acc[mt][2] = b2v.x; acc[mt][3] = b2v.y;
        }
        for (int kt = 16; kt < 32; ++kt) {
            uint2 bv = __ldg(wb2 + kt * KTS);
            unsigned a0, a1, a2, a3, e0, e1, e2, e3;
            ldsm4(a0, a1, a2, a3, aBase0 + (unsigned)(H1OFF + kt * 16) * 2u);
            ldsm4(e0, e1, e2, e3, aBase1 + (unsigned)(H1OFF + kt * 16) * 2u);
            mma16816(acc[0][0], acc[0][1], acc[0][2], acc[0][3], a0, a1, a2, a3, bv.x, bv.y);
            mma16816(acc[1][0], acc[1][1], acc[1][2], acc[1][3], e0, e1, e2, e3, bv.x, bv.y);
        }

        // ---- WAIT(#1): peers' h1(t) published; copy 7 eighths ----
        CL_WAIT();
        #pragma unroll
        for (int pp = 0; pp < 7; ++pp) {
            unsigned v;
            asm volatile("ld.shared::cluster.b32 %0, [%1];" : "=r"(v) : "r"(cp1_rem[pp]));
            asm volatile("st.shared.b32 [%0], %1;" :: "r"(cp1_loc[pp]), "r"(v) : "memory");
        }
        __syncthreads();   // h1(t) full local; all L2A h2 reads done

        // ===== LAYER 2 gates part B: h1(t) tiles (kt 0..15) =====
        for (int kt = 0; kt < 16; ++kt) {
            uint2 bv = __ldg(wb2 + kt * KTS);
            unsigned a0, a1, a2, a3, e0, e1, e2, e3;
            ldsm4(a0, a1, a2, a3, aBase0 + (unsigned)(H1OFF + kt * 16) * 2u);
            ldsm4(e0, e1, e2, e3, aBase1 + (unsigned)(H1OFF + kt * 16) * 2u);
            mma16816(acc[0][0], acc[0][1], acc[0][2], acc[0][3], a0, a1, a2, a3, bv.x, bv.y);
            mma16816(acc[1][0], acc[1][1], acc[1][2], acc[1][3], e0, e1, e2, e3, bv.x, bv.y);
        }

        // ---- L2 update: write OWN h2 eighth + stage x(t+1) ----
        #pragma unroll
        for (int mt = 0; mt < 2; ++mt) {
            float t0 = __shfl_xor_sync(0xffffffffu, acc[mt][0], 1);
            float t1 = __shfl_xor_sync(0xffffffffu, acc[mt][1], 1);
            float t2 = __shfl_xor_sync(0xffffffffu, acc[mt][2], 1);
            float t3 = __shfl_xor_sync(0xffffffffu, acc[mt][3], 1);
            float zi = modd ? t2 : acc[mt][0];
            float zf = modd ? t3 : acc[mt][1];
            float zg = modd ? acc[mt][2] : t0;
            float zo = modd ? acc[mt][3] : t1;
            c2[mt] = sigf(zf) * c2[mt] + sigf(zi) * tanhg(zg);
            float h = sigf(zo) * tanhg(c2[mt]);
            sts16(h2addr + (unsigned)mt * mtoff, __float2half_rn(h));
        }
        if (t + 1 < Tt) {
            int b = tid >> 4, f = tid & 15;
            buf[b * HST + f] =
                __float2half_rn(__ldg(&x[((size_t)(b0 + b) * Tt + (t + 1)) * Ff + f]));
        }
        CL_ARRIVE();       // #2: own h2(t) eighth published
        __syncthreads();   // x(t+1) + own h2 visible locally
    }

    // drain final phase: assemble full h2(T-1) on every CTA (rank 0 needs it)
    CL_WAIT();
    #pragma unroll
    for (int pp = 0; pp < 7; ++pp) {
        unsigned v;
        asm volatile("ld.shared::cluster.b32 %0, [%1];" : "=r"(v) : "r"(cp2_rem[pp]));
        asm volatile("st.shared.b32 [%0], %1;" :: "r"(cp2_loc[pp]), "r"(v) : "memory");
    }
    __syncthreads();

    // ================= linear head: rank 0; warp w -> rows w, w+16 =================
    if (rank == 0) {
        #pragma unroll
        for (int rr = 0; rr < 2; ++rr) {
            const int row = w + 16 * rr;
            float s = 0.f;
            #pragma unroll
            for (int u = lane; u < Hh; u += 32)
                s += __half2float(buf[row * HST + H2OFF + u]) * __ldg(&wlin[u]);
            #pragma unroll
            for (int off = 16; off; off >>= 1) s += __shfl_xor_sync(0xffffffffu, s, off);
            if (lane == 0) out[b0 + row] = s + blin[0];
        }
    }
    CL_ARRIVE(); CL_WAIT();   // keep CTAs resident while peers issue remote ops
}

// ---------------------------------------------------------------------------
extern "C" void kernel_launch(void* const* d_in, const int* in_sizes, int n_in,
                              void* d_out, int out_size) {
    const float* x    = (const float*)d_in[0];
    const float* wih1 = (const float*)d_in[1];
    const float* whh1 = (const float*)d_in[2];
    const float* bih1 = (const float*)d_in[3];
    const float* bhh1 = (const float*)d_in[4];
    const float* wih2 = (const float*)d_in[5];
    const float* whh2 = (const float*)d_in[6];
    const float* bih2 = (const float*)d_in[7];
    const float* bhh2 = (const float*)d_in[8];
    const float* wlin = (const float*)d_in[9];
    const float* blin = (const float*)d_in[10];
    float* out = (float*)d_out;

    prep_kernel<<<(32 * KTS + 255) / 256, 256>>>(wih1, whh1, bih1, bhh1,
                                                 wih2, whh2, bih2, bhh2);
    lstm_kernel<<<NCg, NT>>>(x, wlin, blin, out);
}